// round 5
// baseline (speedup 1.0000x reference)
#include <cuda_runtime.h>
#include <stdint.h>

#define G_MEAN_F 85.384f
#define G_STD_F  53.798f

static __device__ __forceinline__ float warp_sum(float f) {
    #pragma unroll
    for (int o = 16; o; o >>= 1) f += __shfl_down_sync(0xffffffffu, f, o);
    return f;
}

// Compile-time 289-bit validity mask for offset (DR,DC): bit p=r*17+c set iff
// (r,c) is a valid 'a' position: r <= 16-DR and (DC>=0 ? c <= 16-DC : c >= -DC)
template<int DR, int DC>
struct OffMask {
    uint32_t m[10];
    constexpr OffMask() : m{} {
        const int adc = DC < 0 ? -DC : DC;
        for (int r = 0; r <= 16 - DR; ++r)
            for (int c = 0; c < 17; ++c) {
                bool ok = (DC >= 0) ? (c <= 16 - DC) : (c >= adc);
                if (ok) { int p = r * 17 + c; m[p >> 5] |= (1u << (p & 31)); }
            }
    }
};

// GLCM features for one offset from 4 cumulative bit-planes (289-bit bitmaps).
// C[l] = bitmap of (q >= l+1). feat: {contrast, homogeneity, energy, corr, entropy}
template<int DR, int DC>
__device__ __forceinline__ void do_offset(const uint32_t C[4][11], float feat[5])
{
    constexpr int K   = DR * 17 + DC;
    constexpr int WO  = K >> 5;
    constexpr int SH  = K & 31;
    constexpr int ADC = DC < 0 ? -DC : DC;
    constexpr int NW  = ((17 - DR) * 17 + 31) >> 5;
    constexpr int TOT = (17 - DR) * (17 - ADC);
    constexpr OffMask<DR, DC> MK{};

    int Mi[4] = {0,0,0,0}, Mj[4] = {0,0,0,0};
    int M[16];
    #pragma unroll
    for (int i = 0; i < 16; ++i) M[i] = 0;

    #pragma unroll
    for (int w = 0; w < NW; ++w) {
        const uint32_t mk = MK.m[w];
        uint32_t s0 = __funnelshift_r(C[0][w+WO], C[0][w+WO+1], SH) & mk;
        uint32_t s1 = __funnelshift_r(C[1][w+WO], C[1][w+WO+1], SH) & mk;
        uint32_t s2 = __funnelshift_r(C[2][w+WO], C[2][w+WO+1], SH) & mk;
        uint32_t s3 = __funnelshift_r(C[3][w+WO], C[3][w+WO+1], SH) & mk;
        Mj[0] += __popc(s0); Mj[1] += __popc(s1);
        Mj[2] += __popc(s2); Mj[3] += __popc(s3);
        #pragma unroll
        for (int i = 0; i < 4; ++i) {
            uint32_t a = C[i][w];
            Mi[i]    += __popc(a & mk);
            M[i*4+0] += __popc(a & s0);
            M[i*4+1] += __popc(a & s1);
            M[i*4+2] += __popc(a & s2);
            M[i*4+3] += __popc(a & s3);
        }
    }

    // Cumulative table Mc[i][j] = N(a>=i, b>=j) -> cell counts via inclusion-exclusion
    int Mc[25];
    Mc[0] = TOT;
    Mc[1] = Mj[0]; Mc[2] = Mj[1]; Mc[3] = Mj[2]; Mc[4] = Mj[3];
    #pragma unroll
    for (int i = 1; i < 5; ++i) {
        Mc[i*5] = Mi[i-1];
        #pragma unroll
        for (int j = 1; j < 5; ++j) Mc[i*5+j] = M[(i-1)*4 + (j-1)];
    }
    int c[25];
    #pragma unroll
    for (int i = 0; i < 5; ++i)
        #pragma unroll
        for (int j = 0; j < 5; ++j) {
            int v = Mc[i*5+j];
            if (i < 4) v -= Mc[(i+1)*5+j];
            if (j < 4) v -= Mc[i*5+j+1];
            if (i < 4 && j < 4) v += Mc[(i+1)*5+j+1];
            c[i*5+j] = v;
        }

    const float invTot = 1.0f / (2.0f * (float)TOT);

    // symmetrized counts S = C + C^T (upper triangle incl. diag)
    int s00 = c[0]*2,  s11 = c[6]*2,  s22 = c[12]*2, s33 = c[18]*2, s44 = c[24]*2;
    int s01 = c[1]+c[5],   s02 = c[2]+c[10],  s03 = c[3]+c[15],  s04 = c[4]+c[20];
    int s12 = c[7]+c[11],  s13 = c[8]+c[16],  s14 = c[9]+c[21];
    int s23 = c[13]+c[17], s24 = c[14]+c[22];
    int s34 = c[19]+c[23];

    // contrast
    int ci = (s01 + s12 + s23 + s34) + 4*(s02 + s13 + s24) + 9*(s03 + s14) + 16*s04;
    feat[0] = 2.0f * invTot * (float)ci;

    // homogeneity
    float hoU = 0.5f*(float)(s01+s12+s23+s34)
              + 0.2f*(float)(s02+s13+s24)
              + 0.1f*(float)(s03+s14)
              + (1.0f/17.0f)*(float)s04;
    feat[1] = invTot * ((float)(s00+s11+s22+s33+s44) + 2.0f*hoU);

    // energy
    int e2i = s00*s00 + s11*s11 + s22*s22 + s33*s33 + s44*s44
            + 2*(s01*s01 + s02*s02 + s03*s03 + s04*s04
               + s12*s12 + s13*s13 + s14*s14
               + s23*s23 + s24*s24 + s34*s34);
    feat[2] = invTot * sqrtf((float)e2i);

    // correlation (symmetric => Pi == Pj)
    int t1 = s01+s11+s12+s13+s14;
    int t2 = s02+s12+s22+s23+s24;
    int t3 = s03+s13+s23+s33+s34;
    int t4 = s04+s14+s24+s34+s44;
    float mu  = invTot * (float)(t1 + 2*t2 + 3*t3 + 4*t4);
    float e2m = invTot * (float)(t1 + 4*t2 + 9*t3 + 16*t4);
    float varm = e2m - mu * mu;
    int wij = s11 + 4*s22 + 9*s33 + 16*s44
            + 2*(2*s12 + 3*s13 + 4*s14 + 6*s23 + 8*s24 + 12*s34);
    float cov = invTot * (float)wij - mu * mu;
    feat[3] = (varm < 1e-15f) ? 1.0f : (cov / fmaxf(varm, 1e-30f));

    // entropy: off-diagonal cells counted twice
    float ent = 0.0f;
    {
        float g;
        g = (float)s00*invTot; ent += g*__log2f(g+1e-8f);
        g = (float)s11*invTot; ent += g*__log2f(g+1e-8f);
        g = (float)s22*invTot; ent += g*__log2f(g+1e-8f);
        g = (float)s33*invTot; ent += g*__log2f(g+1e-8f);
        g = (float)s44*invTot; ent += g*__log2f(g+1e-8f);
        g = (float)s01*invTot; ent += 2.0f*g*__log2f(g+1e-8f);
        g = (float)s02*invTot; ent += 2.0f*g*__log2f(g+1e-8f);
        g = (float)s03*invTot; ent += 2.0f*g*__log2f(g+1e-8f);
        g = (float)s04*invTot; ent += 2.0f*g*__log2f(g+1e-8f);
        g = (float)s12*invTot; ent += 2.0f*g*__log2f(g+1e-8f);
        g = (float)s13*invTot; ent += 2.0f*g*__log2f(g+1e-8f);
        g = (float)s14*invTot; ent += 2.0f*g*__log2f(g+1e-8f);
        g = (float)s23*invTot; ent += 2.0f*g*__log2f(g+1e-8f);
        g = (float)s24*invTot; ent += 2.0f*g*__log2f(g+1e-8f);
        g = (float)s34*invTot; ent += 2.0f*g*__log2f(g+1e-8f);
    }
    feat[4] = -ent;
}

static __device__ __forceinline__ void emit_feats(const float feat[5], int s1, int s2,
                                                  float valid, float* sacc, bool lane0)
{
    #pragma unroll
    for (int k = 0; k < 5; ++k) {
        float f = warp_sum(feat[k] * valid);
        if (lane0) {
            int base = 8 + 12 * k;
            atomicAdd(&sacc[base + s1], f);
            if (s2 >= 0) atomicAdd(&sacc[base + s2], f);
        }
    }
}

// 64-thread blocks, 12 blocks/SM forces regs <= ~85 -> 24 warps/SM (vs 16 @128 regs)
__global__ void __launch_bounds__(64, 12) glcm_feat_kernel(const float* __restrict__ x,
                                                           float* __restrict__ out)
{
    __shared__ float sacc[68];

    const int tid = threadIdx.x;
    const int b   = blockIdx.y;
    int wi = blockIdx.x * 64 + tid;
    const float valid = (wi < 15376) ? 1.0f : 0.0f;
    if (wi >= 15376) wi = 15375;
    const int ix = wi / 124;
    const int iy = wi - ix * 124;
    const bool lane0 = ((tid & 31) == 0);

    for (int i = tid; i < 68; i += 64) sacc[i] = 0.0f;
    __syncthreads();

    const float* base = x + ((size_t)b << 18) + (size_t)(ix * 4) * 512 + (size_t)(iy * 4);

    const float B1 = 0.5f;
    const float B2 = (float)(85.384 - 53.798);
    const float B3 = 85.384f;
    const float B4 = (float)(85.384 + 53.798);

    // cumulative bit-planes of the whole 17x17 window: C[l] = bitmap(q >= l+1)
    uint32_t C[4][11];
    #pragma unroll
    for (int j = 0; j < 4; ++j)
        #pragma unroll
        for (int w = 0; w < 11; ++w) C[j][w] = 0u;

    float sum = 0.f, sq = 0.f, mxv = 0.f, mnv = 1e30f;

    // ---- load, stats, quantize, build register bitmaps ----
    #pragma unroll
    for (int r = 0; r < 17; ++r) {
        const float* row = base + r * 512;
        const float4* p4 = (const float4*)row;   // iy*4 floats => 16B aligned
        float4 q0 = p4[0], q1 = p4[1], q2 = p4[2], q3 = p4[3];
        float px[17] = {q0.x,q0.y,q0.z,q0.w, q1.x,q1.y,q1.z,q1.w,
                        q2.x,q2.y,q2.z,q2.w, q3.x,q3.y,q3.z,q3.w, row[16]};
        uint32_t g1=0,g2=0,g3=0,g4=0;
        #pragma unroll
        for (int v = 0; v < 17; ++v) {
            float pv = px[v];
            sum += pv;
            float d = pv - G_MEAN_F;
            sq = fmaf(d, d, sq);
            mxv = fmaxf(mxv, pv);
            mnv = fminf(mnv, pv);
            uint32_t bit = 1u << v;
            if (pv >= B1) g1 |= bit;
            if (pv >= B2) g2 |= bit;
            if (pv >= B3) g3 |= bit;
            if (pv >= B4) g4 |= bit;
        }
        const int bp = r * 17;
        const int w0 = bp >> 5;
        const int sh = bp & 31;
        C[0][w0] |= g1 << sh;
        C[1][w0] |= g2 << sh;
        C[2][w0] |= g3 << sh;
        C[3][w0] |= g4 << sh;
        if (sh > 15) {   // row spills into next word (compile-time condition)
            C[0][w0+1] |= g1 >> (32 - sh);
            C[1][w0+1] |= g2 >> (32 - sh);
            C[2][w0+1] |= g3 >> (32 - sh);
            C[3][w0+1] |= g4 >> (32 - sh);
        }
    }

    // ---- stats + histogram channels (0..7) ----
    {
        int P1=0,P2=0,P3=0,P4=0;
        #pragma unroll
        for (int w = 0; w < 10; ++w) {
            P1 += __popc(C[0][w]); P2 += __popc(C[1][w]);
            P3 += __popc(C[2][w]); P4 += __popc(C[3][w]);
        }
        int h1 = P1 - P2, h2 = P2 - P3, h3 = P3 - P4, h4 = P4;

        const float inv289 = 1.0f / 289.0f;
        float mean  = sum * inv289;
        float var0  = fmaxf(sq * inv289 - (mean - G_MEAN_F) * (mean - G_MEAN_F), 0.0f);
        float stdv  = sqrtf(var0);
        float mnorm = mean / G_MEAN_F;

        float f;
        f = warp_sum(mnorm * valid);                     if (lane0) atomicAdd(&sacc[0], f);
        f = warp_sum((stdv / G_STD_F) * valid);          if (lane0) atomicAdd(&sacc[1], f);
        f = warp_sum(((mxv - mnorm) / G_STD_F) * valid); if (lane0) atomicAdd(&sacc[2], f);
        f = warp_sum(((mnorm - mnv) / G_STD_F) * valid); if (lane0) atomicAdd(&sacc[3], f);

        int toti = h1 + h2 + h3 + h4;
        float invt = (toti > 0) ? (1.0f / (float)toti) : 0.0f;
        f = warp_sum((float)h1 * invt * valid);          if (lane0) atomicAdd(&sacc[4], f);
        f = warp_sum((float)h2 * invt * valid);          if (lane0) atomicAdd(&sacc[5], f);
        f = warp_sum((float)h3 * invt * valid);          if (lane0) atomicAdd(&sacc[6], f);
        f = warp_sum((float)h4 * invt * valid);          if (lane0) atomicAdd(&sacc[7], f);
    }

    // ---- GLCM: 10 unique offsets (slots: (1,1)->1&5, (1,-1)->3&7) ----
    float feat[5];
    do_offset<0, 1>(C, feat); emit_feats(feat,  0, -1, valid, sacc, lane0);
    do_offset<1, 1>(C, feat); emit_feats(feat,  1,  5, valid, sacc, lane0);
    do_offset<1, 0>(C, feat); emit_feats(feat,  2, -1, valid, sacc, lane0);
    do_offset<1,-1>(C, feat); emit_feats(feat,  3,  7, valid, sacc, lane0);
    do_offset<0, 2>(C, feat); emit_feats(feat,  4, -1, valid, sacc, lane0);
    do_offset<2, 0>(C, feat); emit_feats(feat,  6, -1, valid, sacc, lane0);
    do_offset<0, 4>(C, feat); emit_feats(feat,  8, -1, valid, sacc, lane0);
    do_offset<3, 3>(C, feat); emit_feats(feat,  9, -1, valid, sacc, lane0);
    do_offset<4, 0>(C, feat); emit_feats(feat, 10, -1, valid, sacc, lane0);
    do_offset<3,-3>(C, feat); emit_feats(feat, 11, -1, valid, sacc, lane0);

    __syncthreads();
    for (int i = tid; i < 68; i += 64)
        atomicAdd(&out[b * 68 + i], sacc[i] * (1.0f / 15376.0f));
}

extern "C" void kernel_launch(void* const* d_in, const int* in_sizes, int n_in,
                              void* d_out, int out_size) {
    const float* x = (const float*)d_in[0];
    float* out = (float*)d_out;
    cudaMemsetAsync(out, 0, (size_t)out_size * sizeof(float), 0);
    dim3 grid(241, 8);   // 241*64 = 15424 >= 15376 windows per image, y = batch
    glcm_feat_kernel<<<grid, 64>>>(x, out);
}

// round 6
// speedup vs baseline: 1.0769x; 1.0769x over previous
#include <cuda_runtime.h>
#include <stdint.h>

#define G_MEAN_F 85.384f
#define G_STD_F  53.798f

static __device__ __forceinline__ float warp_sum(float f) {
    #pragma unroll
    for (int o = 16; o; o >>= 1) f += __shfl_down_sync(0xffffffffu, f, o);
    return f;
}

// Compile-time 289-bit validity mask for offset (DR,DC): bit p=r*17+c set iff
// (r,c) is a valid 'a' position: r <= 16-DR and (DC>=0 ? c <= 16-DC : c >= -DC)
template<int DR, int DC>
struct OffMask {
    uint32_t m[10];
    constexpr OffMask() : m{} {
        const int adc = DC < 0 ? -DC : DC;
        for (int r = 0; r <= 16 - DR; ++r)
            for (int c = 0; c < 17; ++c) {
                bool ok = (DC >= 0) ? (c <= 16 - DC) : (c >= adc);
                if (ok) { int p = r * 17 + c; m[p >> 5] |= (1u << (p & 31)); }
            }
    }
};

// GLCM features for one offset from 4 cumulative bit-planes (289-bit bitmaps).
// C[l] = bitmap of (q >= l+1). feat: {contrast, homogeneity, energy, corr, entropy}
template<int DR, int DC>
__device__ __forceinline__ void do_offset(const uint32_t C[4][11], float feat[5])
{
    constexpr int K   = DR * 17 + DC;
    constexpr int WO  = K >> 5;
    constexpr int SH  = K & 31;
    constexpr int ADC = DC < 0 ? -DC : DC;
    constexpr int NW  = ((17 - DR) * 17 + 31) >> 5;
    constexpr int TOT = (17 - DR) * (17 - ADC);
    constexpr OffMask<DR, DC> MK{};

    int Mi[4] = {0,0,0,0}, Mj[4] = {0,0,0,0};
    int M[16];
    #pragma unroll
    for (int i = 0; i < 16; ++i) M[i] = 0;

    #pragma unroll
    for (int w = 0; w < NW; ++w) {
        const uint32_t mk = MK.m[w];
        uint32_t s0 = __funnelshift_r(C[0][w+WO], C[0][w+WO+1], SH) & mk;
        uint32_t s1 = __funnelshift_r(C[1][w+WO], C[1][w+WO+1], SH) & mk;
        uint32_t s2 = __funnelshift_r(C[2][w+WO], C[2][w+WO+1], SH) & mk;
        uint32_t s3 = __funnelshift_r(C[3][w+WO], C[3][w+WO+1], SH) & mk;
        Mj[0] += __popc(s0); Mj[1] += __popc(s1);
        Mj[2] += __popc(s2); Mj[3] += __popc(s3);
        #pragma unroll
        for (int i = 0; i < 4; ++i) {
            uint32_t a = C[i][w];
            Mi[i]    += __popc(a & mk);
            M[i*4+0] += __popc(a & s0);
            M[i*4+1] += __popc(a & s1);
            M[i*4+2] += __popc(a & s2);
            M[i*4+3] += __popc(a & s3);
        }
    }

    // Cumulative table Mc[i][j] = N(a>=i, b>=j) -> cell counts via inclusion-exclusion
    int Mc[25];
    Mc[0] = TOT;
    Mc[1] = Mj[0]; Mc[2] = Mj[1]; Mc[3] = Mj[2]; Mc[4] = Mj[3];
    #pragma unroll
    for (int i = 1; i < 5; ++i) {
        Mc[i*5] = Mi[i-1];
        #pragma unroll
        for (int j = 1; j < 5; ++j) Mc[i*5+j] = M[(i-1)*4 + (j-1)];
    }
    int c[25];
    #pragma unroll
    for (int i = 0; i < 5; ++i)
        #pragma unroll
        for (int j = 0; j < 5; ++j) {
            int v = Mc[i*5+j];
            if (i < 4) v -= Mc[(i+1)*5+j];
            if (j < 4) v -= Mc[i*5+j+1];
            if (i < 4 && j < 4) v += Mc[(i+1)*5+j+1];
            c[i*5+j] = v;
        }

    const float invTot = 1.0f / (2.0f * (float)TOT);

    // symmetrized counts S = C + C^T (upper triangle incl. diag)
    int s00 = c[0]*2,  s11 = c[6]*2,  s22 = c[12]*2, s33 = c[18]*2, s44 = c[24]*2;
    int s01 = c[1]+c[5],   s02 = c[2]+c[10],  s03 = c[3]+c[15],  s04 = c[4]+c[20];
    int s12 = c[7]+c[11],  s13 = c[8]+c[16],  s14 = c[9]+c[21];
    int s23 = c[13]+c[17], s24 = c[14]+c[22];
    int s34 = c[19]+c[23];

    // contrast
    int ci = (s01 + s12 + s23 + s34) + 4*(s02 + s13 + s24) + 9*(s03 + s14) + 16*s04;
    feat[0] = 2.0f * invTot * (float)ci;

    // homogeneity
    float hoU = 0.5f*(float)(s01+s12+s23+s34)
              + 0.2f*(float)(s02+s13+s24)
              + 0.1f*(float)(s03+s14)
              + (1.0f/17.0f)*(float)s04;
    feat[1] = invTot * ((float)(s00+s11+s22+s33+s44) + 2.0f*hoU);

    // energy
    int e2i = s00*s00 + s11*s11 + s22*s22 + s33*s33 + s44*s44
            + 2*(s01*s01 + s02*s02 + s03*s03 + s04*s04
               + s12*s12 + s13*s13 + s14*s14
               + s23*s23 + s24*s24 + s34*s34);
    feat[2] = invTot * sqrtf((float)e2i);

    // correlation (symmetric => Pi == Pj)
    int t1 = s01+s11+s12+s13+s14;
    int t2 = s02+s12+s22+s23+s24;
    int t3 = s03+s13+s23+s33+s34;
    int t4 = s04+s14+s24+s34+s44;
    float mu  = invTot * (float)(t1 + 2*t2 + 3*t3 + 4*t4);
    float e2m = invTot * (float)(t1 + 4*t2 + 9*t3 + 16*t4);
    float varm = e2m - mu * mu;
    int wij = s11 + 4*s22 + 9*s33 + 16*s44
            + 2*(2*s12 + 3*s13 + 4*s14 + 6*s23 + 8*s24 + 12*s34);
    float cov = invTot * (float)wij - mu * mu;
    feat[3] = (varm < 1e-15f) ? 1.0f : (cov / fmaxf(varm, 1e-30f));

    // entropy: off-diagonal cells counted twice
    float ent = 0.0f;
    {
        float g;
        g = (float)s00*invTot; ent += g*__log2f(g+1e-8f);
        g = (float)s11*invTot; ent += g*__log2f(g+1e-8f);
        g = (float)s22*invTot; ent += g*__log2f(g+1e-8f);
        g = (float)s33*invTot; ent += g*__log2f(g+1e-8f);
        g = (float)s44*invTot; ent += g*__log2f(g+1e-8f);
        g = (float)s01*invTot; ent += 2.0f*g*__log2f(g+1e-8f);
        g = (float)s02*invTot; ent += 2.0f*g*__log2f(g+1e-8f);
        g = (float)s03*invTot; ent += 2.0f*g*__log2f(g+1e-8f);
        g = (float)s04*invTot; ent += 2.0f*g*__log2f(g+1e-8f);
        g = (float)s12*invTot; ent += 2.0f*g*__log2f(g+1e-8f);
        g = (float)s13*invTot; ent += 2.0f*g*__log2f(g+1e-8f);
        g = (float)s14*invTot; ent += 2.0f*g*__log2f(g+1e-8f);
        g = (float)s23*invTot; ent += 2.0f*g*__log2f(g+1e-8f);
        g = (float)s24*invTot; ent += 2.0f*g*__log2f(g+1e-8f);
        g = (float)s34*invTot; ent += 2.0f*g*__log2f(g+1e-8f);
    }
    feat[4] = -ent;
}

static __device__ __forceinline__ void emit_feats(const float feat[5], int s1, int s2,
                                                  float valid, float* sacc, bool lane0)
{
    #pragma unroll
    for (int k = 0; k < 5; ++k) {
        float f = warp_sum(feat[k] * valid);
        if (lane0) {
            int base = 8 + 12 * k;
            atomicAdd(&sacc[base + s1], f);
            if (s2 >= 0) atomicAdd(&sacc[base + s2], f);
        }
    }
}

// 128 threads, min 5 blocks/SM => reg budget 102 (no spills expected), 20 warps/SM
__global__ void __launch_bounds__(128, 5) glcm_feat_kernel(const float* __restrict__ x,
                                                           float* __restrict__ out)
{
    __shared__ float sacc[68];

    const int tid = threadIdx.x;
    const int b   = blockIdx.y;
    int wi = blockIdx.x * 128 + tid;
    const float valid = (wi < 15376) ? 1.0f : 0.0f;
    if (wi >= 15376) wi = 15375;
    const int ix = wi / 124;
    const int iy = wi - ix * 124;
    const bool lane0 = ((tid & 31) == 0);

    for (int i = tid; i < 68; i += 128) sacc[i] = 0.0f;
    __syncthreads();

    const float* base = x + ((size_t)b << 18) + (size_t)(ix * 4) * 512 + (size_t)(iy * 4);

    const float B1 = 0.5f;
    const float B2 = (float)(85.384 - 53.798);
    const float B3 = 85.384f;
    const float B4 = (float)(85.384 + 53.798);

    // cumulative bit-planes of the whole 17x17 window: C[l] = bitmap(q >= l+1)
    uint32_t C[4][11];
    #pragma unroll
    for (int j = 0; j < 4; ++j)
        #pragma unroll
        for (int w = 0; w < 11; ++w) C[j][w] = 0u;

    float sum = 0.f, sq = 0.f, mxv = 0.f, mnv = 1e30f;

    // ---- load, stats, quantize, build register bitmaps ----
    #pragma unroll
    for (int r = 0; r < 17; ++r) {
        const float* row = base + r * 512;
        const float4* p4 = (const float4*)row;   // iy*4 floats => 16B aligned
        float4 q0 = p4[0], q1 = p4[1], q2 = p4[2], q3 = p4[3];
        float px[17] = {q0.x,q0.y,q0.z,q0.w, q1.x,q1.y,q1.z,q1.w,
                        q2.x,q2.y,q2.z,q2.w, q3.x,q3.y,q3.z,q3.w, row[16]};
        uint32_t g1=0,g2=0,g3=0,g4=0;
        #pragma unroll
        for (int v = 0; v < 17; ++v) {
            float pv = px[v];
            sum += pv;
            float d = pv - G_MEAN_F;
            sq = fmaf(d, d, sq);
            mxv = fmaxf(mxv, pv);
            mnv = fminf(mnv, pv);
            uint32_t bit = 1u << v;
            if (pv >= B1) g1 |= bit;
            if (pv >= B2) g2 |= bit;
            if (pv >= B3) g3 |= bit;
            if (pv >= B4) g4 |= bit;
        }
        const int bp = r * 17;
        const int w0 = bp >> 5;
        const int sh = bp & 31;
        C[0][w0] |= g1 << sh;
        C[1][w0] |= g2 << sh;
        C[2][w0] |= g3 << sh;
        C[3][w0] |= g4 << sh;
        if (sh > 15) {   // row spills into next word (compile-time condition)
            C[0][w0+1] |= g1 >> (32 - sh);
            C[1][w0+1] |= g2 >> (32 - sh);
            C[2][w0+1] |= g3 >> (32 - sh);
            C[3][w0+1] |= g4 >> (32 - sh);
        }
    }

    // ---- stats + histogram channels (0..7) ----
    {
        int P1=0,P2=0,P3=0,P4=0;
        #pragma unroll
        for (int w = 0; w < 10; ++w) {
            P1 += __popc(C[0][w]); P2 += __popc(C[1][w]);
            P3 += __popc(C[2][w]); P4 += __popc(C[3][w]);
        }
        int h1 = P1 - P2, h2 = P2 - P3, h3 = P3 - P4, h4 = P4;

        const float inv289 = 1.0f / 289.0f;
        float mean  = sum * inv289;
        float var0  = fmaxf(sq * inv289 - (mean - G_MEAN_F) * (mean - G_MEAN_F), 0.0f);
        float stdv  = sqrtf(var0);
        float mnorm = mean / G_MEAN_F;

        float f;
        f = warp_sum(mnorm * valid);                     if (lane0) atomicAdd(&sacc[0], f);
        f = warp_sum((stdv / G_STD_F) * valid);          if (lane0) atomicAdd(&sacc[1], f);
        f = warp_sum(((mxv - mnorm) / G_STD_F) * valid); if (lane0) atomicAdd(&sacc[2], f);
        f = warp_sum(((mnorm - mnv) / G_STD_F) * valid); if (lane0) atomicAdd(&sacc[3], f);

        int toti = h1 + h2 + h3 + h4;
        float invt = (toti > 0) ? (1.0f / (float)toti) : 0.0f;
        f = warp_sum((float)h1 * invt * valid);          if (lane0) atomicAdd(&sacc[4], f);
        f = warp_sum((float)h2 * invt * valid);          if (lane0) atomicAdd(&sacc[5], f);
        f = warp_sum((float)h3 * invt * valid);          if (lane0) atomicAdd(&sacc[6], f);
        f = warp_sum((float)h4 * invt * valid);          if (lane0) atomicAdd(&sacc[7], f);
    }

    // ---- GLCM: 10 unique offsets (slots: (1,1)->1&5, (1,-1)->3&7) ----
    float feat[5];
    do_offset<0, 1>(C, feat); emit_feats(feat,  0, -1, valid, sacc, lane0);
    do_offset<1, 1>(C, feat); emit_feats(feat,  1,  5, valid, sacc, lane0);
    do_offset<1, 0>(C, feat); emit_feats(feat,  2, -1, valid, sacc, lane0);
    do_offset<1,-1>(C, feat); emit_feats(feat,  3,  7, valid, sacc, lane0);
    do_offset<0, 2>(C, feat); emit_feats(feat,  4, -1, valid, sacc, lane0);
    do_offset<2, 0>(C, feat); emit_feats(feat,  6, -1, valid, sacc, lane0);
    do_offset<0, 4>(C, feat); emit_feats(feat,  8, -1, valid, sacc, lane0);
    do_offset<3, 3>(C, feat); emit_feats(feat,  9, -1, valid, sacc, lane0);
    do_offset<4, 0>(C, feat); emit_feats(feat, 10, -1, valid, sacc, lane0);
    do_offset<3,-3>(C, feat); emit_feats(feat, 11, -1, valid, sacc, lane0);

    __syncthreads();
    if (tid < 68) atomicAdd(&out[b * 68 + tid], sacc[tid] * (1.0f / 15376.0f));
}

extern "C" void kernel_launch(void* const* d_in, const int* in_sizes, int n_in,
                              void* d_out, int out_size) {
    const float* x = (const float*)d_in[0];
    float* out = (float*)d_out;
    cudaMemsetAsync(out, 0, (size_t)out_size * sizeof(float), 0);
    dim3 grid(121, 8);   // 121*128 = 15488 >= 15376 windows per image, y = batch
    glcm_feat_kernel<<<grid, 128>>>(x, out);
}